// round 12
// baseline (speedup 1.0000x reference)
#include <cuda_runtime.h>
#include <math.h>
#include <stdint.h>

#define BB 4
#define SS 2048
#define HH 1024
#define INNERD 512
#define RAD 8
#define KSTEPS 4
#define LAMv 0.1f
#define MU_MAXV 10.0f

#define BSH (BB*SS*HH)

// mu lookup table: z(dist, cos), pre-softplus.
#define TABD 256
#define TABC 64
#define TAB_HD 0.5f
#define TAB_HC (2.0f / (TABC - 1))

// Scratch (no cudaMalloc allowed). Ping-pong state buffers.
__device__ float g_q[BSH];
__device__ float g_stateA[BSH];
__device__ float g_stateB[BSH];
__device__ float g_nsqH[2 * BB * SS];          // per-column-half partials
__device__ float g_dotsH[2 * BB * RAD * SS];   // per-column-half partials
__device__ float g_ztab[TABD * TABC];

__device__ __forceinline__ float to_tf32(float x) {
    float r;
    asm("cvt.rna.tf32.f32 %0, %1;" : "=f"(r) : "f"(x));
    return r;
}
__device__ __forceinline__ uint32_t tf32_bits(float x) {
    return __float_as_uint(to_tf32(x));
}
__device__ __forceinline__ void cp_async16(uint32_t s, const void* g) {
    asm volatile("cp.async.ca.shared.global [%0], [%1], 16;" :: "r"(s), "l"(g));
}
__device__ __forceinline__ void cp_commit() {
    asm volatile("cp.async.commit_group;");
}
template<int N>
__device__ __forceinline__ void cp_wait() {
    asm volatile("cp.async.wait_group %0;" :: "n"(N));
}

// mu from (nsqi, nsqj, dot) via bilinear table interp + softplus + clamp.
__device__ __forceinline__ float mu_from(float nsqi, float nsqj, float dot) {
    float dist = sqrtf(fmaxf(nsqi + nsqj - 2.f * dot, 0.f));
    float ni = fmaxf(sqrtf(nsqi), 1e-6f);
    float nj = fmaxf(sqrtf(nsqj), 1e-6f);
    float cosv = dot / (ni * nj);

    float Df = dist * (1.f / TAB_HD);
    int di = (int)Df;
    di = min(max(di, 0), TABD - 2);
    float fd = fminf(fmaxf(Df - (float)di, 0.f), 1.f);

    float Cf = (cosv + 1.f) * (1.f / TAB_HC);
    int cj = (int)Cf;
    cj = min(max(cj, 0), TABC - 2);
    float fc = fminf(fmaxf(Cf - (float)cj, 0.f), 1.f);

    const float* t0 = &g_ztab[di * TABC + cj];
    float z00 = t0[0],    z01 = t0[1];
    float z10 = t0[TABC], z11 = t0[TABC + 1];
    float zl = z00 + fc * (z01 - z00);
    float zh = z10 + fc * (z11 - z10);
    float z  = zl + fd * (zh - zl);

    float sp = fmaxf(z, 0.f) + log1pf(expf(-fabsf(z)));
    return fminf(sp + 1e-5f, MU_MAXV);
}

// ---------------------------------------------------------------------------
// GEMM (TF32 mma.sync, cp.async double-buffered): q = hidden @ Wq + bq.
// ---------------------------------------------------------------------------
#define TM 128
#define TN 128
#define TK 32
#define AS_LD (TK + 4)
#define BS_LD (TN + 4)
#define AS_STAGE (TM * AS_LD)
#define BS_STAGE (TK * BS_LD)
#define GEMM_SMEM ((2*AS_STAGE + 2*BS_STAGE) * sizeof(float))

__global__ __launch_bounds__(256) void gemm_tf32_kernel(
    const float* __restrict__ A,
    const float* __restrict__ W,
    const float* __restrict__ bias)
{
    extern __shared__ float sm[];
    float* As = sm;
    float* Bs = sm + 2 * AS_STAGE;
    uint32_t as_u = (uint32_t)__cvta_generic_to_shared(As);
    uint32_t bs_u = (uint32_t)__cvta_generic_to_shared(Bs);

    const int N = HH, K = HH;
    int tid = threadIdx.x;
    int m0 = blockIdx.y * TM;
    int n0 = blockIdx.x * TN;
    int wid = tid >> 5, lane = tid & 31;
    int wm = (wid & 3) * 32;
    int wn = (wid >> 2) * 64;
    int gid = lane >> 2, tig = lane & 3;

    float acc[2][8][4];
#pragma unroll
    for (int mt = 0; mt < 2; mt++)
#pragma unroll
        for (int nt = 0; nt < 8; nt++)
#pragma unroll
            for (int c = 0; c < 4; c++) acc[mt][nt][c] = 0.f;

    int am[4], ak[4], bk[4], bn[4];
#pragma unroll
    for (int r = 0; r < 4; r++) {
        int f = tid + 256 * r;
        am[r] = f >> 3;  ak[r] = (f & 7) * 4;
        bk[r] = f >> 5;  bn[r] = (f & 31) * 4;
    }

#define LOAD_STAGE(s, k0)                                                     \
    {                                                                         \
        _Pragma("unroll")                                                     \
        for (int r = 0; r < 4; r++) {                                         \
            cp_async16(as_u + (((s)*TM + am[r]) * AS_LD + ak[r]) * 4,         \
                       &A[(size_t)(m0 + am[r]) * K + (k0) + ak[r]]);          \
            cp_async16(bs_u + (((s)*TK + bk[r]) * BS_LD + bn[r]) * 4,         \
                       &W[(size_t)((k0) + bk[r]) * N + n0 + bn[r]]);          \
        }                                                                     \
        cp_commit();                                                          \
    }

    LOAD_STAGE(0, 0);

    const int NIT = K / TK;   // 32
    for (int it = 0; it < NIT; it++) {
        if (it + 1 < NIT) {
            LOAD_STAGE((it + 1) & 1, (it + 1) * TK);
            cp_wait<1>();
        } else {
            cp_wait<0>();
        }
        __syncthreads();

        int buf = it & 1;
        const float* Ab = As + buf * AS_STAGE;
        const float* Bb = Bs + buf * BS_STAGE;
#pragma unroll
        for (int ks = 0; ks < 4; ks++) {
            int kb = ks * 8;
            uint32_t af[2][4];
#pragma unroll
            for (int mt = 0; mt < 2; mt++) {
                int rm = wm + mt * 16 + gid;
                af[mt][0] = tf32_bits(Ab[rm * AS_LD + kb + tig]);
                af[mt][1] = tf32_bits(Ab[(rm + 8) * AS_LD + kb + tig]);
                af[mt][2] = tf32_bits(Ab[rm * AS_LD + kb + tig + 4]);
                af[mt][3] = tf32_bits(Ab[(rm + 8) * AS_LD + kb + tig + 4]);
            }
            uint32_t bf[8][2];
#pragma unroll
            for (int nt = 0; nt < 8; nt++) {
                int cn = wn + nt * 8 + gid;
                bf[nt][0] = tf32_bits(Bb[(kb + tig) * BS_LD + cn]);
                bf[nt][1] = tf32_bits(Bb[(kb + tig + 4) * BS_LD + cn]);
            }
#pragma unroll
            for (int mt = 0; mt < 2; mt++)
#pragma unroll
                for (int nt = 0; nt < 8; nt++) {
                    asm volatile(
                        "mma.sync.aligned.m16n8k8.row.col.f32.tf32.tf32.f32 "
                        "{%0,%1,%2,%3}, {%4,%5,%6,%7}, {%8,%9}, {%0,%1,%2,%3};"
                        : "+f"(acc[mt][nt][0]), "+f"(acc[mt][nt][1]),
                          "+f"(acc[mt][nt][2]), "+f"(acc[mt][nt][3])
                        : "r"(af[mt][0]), "r"(af[mt][1]),
                          "r"(af[mt][2]), "r"(af[mt][3]),
                          "r"(bf[nt][0]), "r"(bf[nt][1]));
                }
        }
        __syncthreads();
    }

#pragma unroll
    for (int mt = 0; mt < 2; mt++) {
        int row0 = m0 + wm + mt * 16 + gid;
#pragma unroll
        for (int nt = 0; nt < 8; nt++) {
            int col = n0 + wn + nt * 8 + 2 * tig;
            float bx = bias[col], by = bias[col + 1];
            float2 v0 = make_float2(acc[mt][nt][0] + bx, acc[mt][nt][1] + by);
            float2 v1 = make_float2(acc[mt][nt][2] + bx, acc[mt][nt][3] + by);
            *(float2*)&g_q[(size_t)row0 * N + col] = v0;
            *(float2*)&g_q[(size_t)(row0 + 8) * N + col] = v1;
        }
    }
}

// ---------------------------------------------------------------------------
// Build z-table (runs once). Also zeroes energy slots.
// ---------------------------------------------------------------------------
__global__ __launch_bounds__(256) void build_tab_kernel(
    const float* __restrict__ W1, const float* __restrict__ b1,
    const float* __restrict__ W2, const float* __restrict__ b2,
    float* __restrict__ out)
{
    if (blockIdx.x == 0 && threadIdx.x < BB)
        out[(size_t)BSH + threadIdx.x] = 0.f;

    int w = (blockIdx.x * 256 + threadIdx.x) >> 5;
    int lane = threadIdx.x & 31;
    if (w >= TABD * TABC) return;
    float D = (float)(w / TABC) * TAB_HD;
    float c = -1.f + (float)(w % TABC) * TAB_HC;

    const float IS2 = 0.70710678118654752f;
    float z = 0.f;
#pragma unroll 4
    for (int k = lane; k < INNERD; k += 32) {
        float x = fmaf(D, W1[k], fmaf(c, W1[INNERD + k], b1[k]));
        float g = 0.5f * x * (1.f + erff(x * IS2));
        z = fmaf(g, W2[k], z);
    }
#pragma unroll
    for (int o = 16; o > 0; o >>= 1)
        z += __shfl_xor_sync(0xffffffffu, z, o);
    if (lane == 0) g_ztab[w] = z + b2[0];
}

// ---------------------------------------------------------------------------
// Tiled dots, COLUMN-HALVED: blockIdx.z = half (512 cols). Partial sums into
// g_nsqH / g_dotsH.
// ---------------------------------------------------------------------------
#define DT 24
#define DROWS 32
#define DHALF 512
#define DOTS_SMEM (DROWS * DHALF * sizeof(float))

__global__ __launch_bounds__(256) void dots_half_kernel(const float* __restrict__ src)
{
    extern __shared__ float sh[];  // DROWS * DHALF
    int tid = threadIdx.x;
    int b = blockIdx.y;
    int half = blockIdx.z;
    int i0 = blockIdx.x * DT;
    int cb = half * DHALF;

#pragma unroll
    for (int s = 0; s < (DROWS * DHALF / 4) / 256; s++) {   // 16 iters
        int slot = tid + 256 * s;
        int row = slot >> 7;
        int c4 = slot & 127;
        int i = i0 + row;
        if (i < SS)
            ((float4*)(sh + (size_t)row * DHALF))[c4] =
                ((const float4*)(src + ((size_t)b * SS + i) * HH + cb))[c4];
    }
    __syncthreads();

    int w = tid >> 5, lane = tid & 31;
    size_t hn = (size_t)half * BB * SS;
    size_t hd = (size_t)half * BB * RAD * SS;
#pragma unroll
    for (int nn = 0; nn < 3; nn++) {
        int ln = w * 3 + nn;          // 0..23
        int i = i0 + ln;
        if (i >= SS) continue;
        const float4* arow = (const float4*)(sh + (size_t)ln * DHALF);
        float4 a[4];
#pragma unroll
        for (int r = 0; r < 4; r++) a[r] = arow[lane + 32 * r];

#pragma unroll
        for (int d = 0; d <= RAD; d++) {
            if (d > 0 && i + d >= SS) break;
            float sum = 0.f;
            if (d == 0) {
#pragma unroll
                for (int r = 0; r < 4; r++)
                    sum += a[r].x*a[r].x + a[r].y*a[r].y + a[r].z*a[r].z + a[r].w*a[r].w;
            } else {
                const float4* crow = (const float4*)(sh + (size_t)(ln + d) * DHALF);
#pragma unroll
                for (int r = 0; r < 4; r++) {
                    float4 c = crow[lane + 32 * r];
                    sum += a[r].x*c.x + a[r].y*c.y + a[r].z*c.z + a[r].w*c.w;
                }
            }
#pragma unroll
            for (int o = 16; o > 0; o >>= 1)
                sum += __shfl_xor_sync(0xffffffffu, sum, o);
            if (lane == 0) {
                if (d == 0) g_nsqH[hn + b * SS + i] = sum;
                else g_dotsH[hd + ((size_t)b * RAD + (d - 1)) * SS + i] = sum;
            }
        }
    }
}

// ---------------------------------------------------------------------------
// Fused mu+deg+lap+update+smooth, COLUMN-TILED: LT=48 rows x 256 cols.
// mu computed INLINE per block window via table (no mu kernel, no g_mu).
// ---------------------------------------------------------------------------
#define LT 48
#define LCW 256
#define LSROWS (LT + 18)     // 66: state rows [i0-9, i0+LT+9)
#define LTROWS (LT + 2)      // 50: tmp rows [i0-1, i0+LT+1)
#define NANCH (LT + 26)      // 74: mu anchors [i0-17, i0+LT+9)
#define NNODE (LT + 34)      // 82: nsq nodes [i0-17, i0+LT+17)
#define LAPS_SMEM (((size_t)LSROWS * LCW + NNODE + NANCH * 8 + \
                    LTROWS * 16 + LTROWS + LSROWS) * sizeof(float))

__global__ __launch_bounds__(128) void lapsmooth_kernel(
    const float* __restrict__ src, float* __restrict__ dst, float eta)
{
    extern __shared__ float sh[];
    float* st   = sh;                           // LSROWS * LCW
    float* nsqs = st + (size_t)LSROWS * LCW;    // NNODE
    float* mus  = nsqs + NNODE;                 // NANCH * 8
    float* cof  = mus + NANCH * 8;              // LTROWS * 16
    float* csm  = cof + LTROWS * 16;            // LTROWS
    float* isqs = csm + LTROWS;                 // LSROWS

    int tid = threadIdx.x;
    int b = blockIdx.z;
    int i0 = blockIdx.x * LT;
    int cb = blockIdx.y * LCW;
    int lc = tid * 2;

    // load state rows [i0-9, i0+LT+9)
#pragma unroll 4
    for (int r = 0; r < LSROWS; r++) {
        int j = i0 - 9 + r;
        if (j >= 0 && j < SS)
            *(float2*)&st[(size_t)r * LCW + lc] =
                *(const float2*)&src[((size_t)b * SS + j) * HH + cb + lc];
    }
    // nsq for nodes [i0-17, i0+LT+17)
    for (int s = tid; s < NNODE; s += 128) {
        int n = i0 - 17 + s;
        float v = 0.f;
        if (n >= 0 && n < SS)
            v = g_nsqH[b * SS + n] + g_nsqH[(size_t)BB * SS + b * SS + n];
        nsqs[s] = v;
    }
    __syncthreads();

    // mu for anchors [i0-17, i0+LT+9) x d=1..8 (table lookup)
    for (int e = tid; e < NANCH * 8; e += 128) {
        int ar = e >> 3;
        int d = (e & 7) + 1;
        int i = i0 - 17 + ar;
        int j = i + d;
        float m = 0.f;
        if (i >= 0 && j < SS) {
            size_t slot = ((size_t)b * RAD + (d - 1)) * SS + i;
            float dot = g_dotsH[slot] + g_dotsH[(size_t)BB * RAD * SS + slot];
            m = mu_from(nsqs[ar], nsqs[ar + d], dot);
        }
        mus[e] = m;
    }
    __syncthreads();

    // deg -> isq for nodes [i0-9, i0+LT+9); node n = i0-9+s has anchor idx s+8
    for (int s = tid; s < LSROWS; s += 128) {
        int n = i0 - 9 + s;
        float isq = 0.f;
        if (n >= 0 && n < SS) {
            float deg = 0.f;
#pragma unroll
            for (int d = 1; d <= RAD; d++) {
                deg += mus[(s + 8) * 8 + d - 1];        // edge (n, n+d); 0 if invalid
                deg += mus[(s + 8 - d) * 8 + d - 1];    // edge (n-d, d); 0 if invalid
            }
            isq = rsqrtf(fmaxf(deg, 1e-6f));
        }
        isqs[s] = isq;
    }
    __syncthreads();

    // coefficients for LTROWS tmp rows (clamped je)
    for (int idx = tid; idx < LTROWS * 16; idx += 128) {
        int jl = idx >> 4;
        int k = idx & 15;
        int j = i0 - 1 + jl;
        int je = min(max(j, 0), SS - 1);
        int d = (k >> 1) + 1;
        int ae = je - (i0 - 17);            // anchor idx of je
        float c;
        if (!(k & 1)) {                      // + direction: edge (je, je+d)
            int jn = je + d;
            c = mus[ae * 8 + d - 1] * isqs[je - (i0 - 9)] *
                isqs[min(jn - (i0 - 9), LSROWS - 1)];
        } else {                             // - direction: edge (je-d, d)
            int jn = je - d;
            c = mus[(ae - d) * 8 + d - 1] * isqs[je - (i0 - 9)] *
                isqs[max(jn - (i0 - 9), 0)];
        }
        cof[idx] = c;
    }
    __syncthreads();
    if (tid < LTROWS) {
        float s = 0.f;
#pragma unroll
        for (int k = 0; k < 16; k++) s += cof[tid * 16 + k];
        csm[tid] = s;
    }
    __syncthreads();

    float2 t0, t1, t2;
#pragma unroll 2
    for (int jl = 0; jl < LTROWS; jl++) {
        int j = i0 - 1 + jl;
        int je = min(max(j, 0), SS - 1);
        int jloc = je - i0 + 9;
        float2 si = *(const float2*)&st[(size_t)jloc * LCW + lc];
        float cs = csm[jl];
        float2 acc;
        acc.x = cs * si.x; acc.y = cs * si.y;
#pragma unroll
        for (int k = 0; k < 16; k++) {
            float c = cof[jl * 16 + k];
            if (c != 0.f) {
                int d = (k >> 1) + 1;
                int off = (k & 1) ? -d : d;
                float2 sj = *(const float2*)&st[(size_t)(jloc + off) * LCW + lc];
                acc.x = fmaf(-c, sj.x, acc.x);
                acc.y = fmaf(-c, sj.y, acc.y);
            }
        }
        float2 qv = *(const float2*)&g_q[((size_t)b * SS + je) * HH + cb + lc];
        float2 tv;
        tv.x = si.x - eta * (acc.x - qv.x);
        tv.y = si.y - eta * (acc.y - qv.y);
        t0 = t1; t1 = t2; t2 = tv;
        if (jl >= 2) {
            int i = i0 + jl - 2;
            if (i < SS) {
                float2 o;
                o.x = t1.x - LAMv * (2.f * t1.x - t0.x - t2.x);
                o.y = t1.y - LAMv * (2.f * t1.y - t0.y - t2.y);
                *(float2*)&dst[((size_t)b * SS + i) * HH + cb + lc] = o;
            }
        }
    }
}

// ---------------------------------------------------------------------------
// Fused final energy: mu computed inline from state_3 partials (nsqH/dotsH),
// dsq from final-state tile. energy += 0.5 * sum mu_e * ||s_i - s_j||^2.
// ---------------------------------------------------------------------------
#define EROWS 32
#define EDT 24
#define ENERGY_SMEM ((EROWS * HH + EDT * 8) * sizeof(float))

__global__ __launch_bounds__(256) void energy_tiled_kernel(
    const float* __restrict__ src, float* __restrict__ out)
{
    extern __shared__ float sh[];            // EROWS*HH + EDT*8
    float* emus = sh + EROWS * HH;
    int tid = threadIdx.x;
    int b = blockIdx.y;
    int i0 = blockIdx.x * EDT;

#pragma unroll
    for (int r = 0; r < EROWS; r++) {
        int i = i0 + r;
        if (i < SS)
            ((float4*)(sh + (size_t)r * HH))[tid] =
                ((const float4*)(src + ((size_t)b * SS + i) * HH))[tid];
    }
    // mu for this block's edges from state_3 partials
    for (int e = tid; e < EDT * 8; e += 256) {
        int a = e >> 3;
        int d = (e & 7) + 1;
        int i = i0 + a;
        int j = i + d;
        float m = 0.f;
        if (i < SS && j < SS) {
            size_t slot = ((size_t)b * RAD + (d - 1)) * SS + i;
            float dot = g_dotsH[slot] + g_dotsH[(size_t)BB * RAD * SS + slot];
            float nsqi = g_nsqH[b * SS + i] + g_nsqH[(size_t)BB * SS + b * SS + i];
            float nsqj = g_nsqH[b * SS + j] + g_nsqH[(size_t)BB * SS + b * SS + j];
            m = mu_from(nsqi, nsqj, dot);
        }
        emus[e] = m;
    }
    __syncthreads();

    int w = tid >> 5, lane = tid & 31;
    float wpart = 0.f;
#pragma unroll
    for (int nn = 0; nn < 3; nn++) {
        int ln = w * 3 + nn;
        int i = i0 + ln;
        if (i >= SS) continue;
        const float4* arow = (const float4*)(sh + (size_t)ln * HH);
        float4 a[8];
#pragma unroll
        for (int r = 0; r < 8; r++) a[r] = arow[lane + 32 * r];
#pragma unroll
        for (int d = 1; d <= RAD; d++) {
            if (i + d >= SS) break;
            const float4* crow = (const float4*)(sh + (size_t)(ln + d) * HH);
            float sum = 0.f;
#pragma unroll
            for (int r = 0; r < 8; r++) {
                float4 c = crow[lane + 32 * r];
                float dx = a[r].x - c.x, dy = a[r].y - c.y;
                float dz = a[r].z - c.z, dw = a[r].w - c.w;
                sum += dx*dx + dy*dy + dz*dz + dw*dw;
            }
#pragma unroll
            for (int o = 16; o > 0; o >>= 1)
                sum += __shfl_xor_sync(0xffffffffu, sum, o);
            if (lane == 0)
                wpart += emus[ln * 8 + d - 1] * sum;
        }
    }
    __shared__ float red[8];
    if (lane == 0) red[w] = wpart;
    __syncthreads();
    if (tid == 0) {
        float s = 0.f;
#pragma unroll
        for (int ww = 0; ww < 8; ww++) s += red[ww];
        atomicAdd(&out[(size_t)BSH + b], 0.5f * s);
    }
}

// ---------------------------------------------------------------------------
// out = layernorm(final + hidden) * gamma + beta
// ---------------------------------------------------------------------------
__global__ __launch_bounds__(256) void ln_kernel(
    const float* __restrict__ fin,
    const float* __restrict__ hidden,
    const float* __restrict__ gamma, const float* __restrict__ beta,
    float* __restrict__ out)
{
    int i = blockIdx.x, b = blockIdx.y;
    int tid = threadIdx.x;
    size_t base = ((size_t)b * SS + i) * HH + tid * 4;
    float4 s = *(const float4*)&fin[base];
    float4 h = *(const float4*)&hidden[base];
    float4 x;
    x.x = s.x + h.x; x.y = s.y + h.y; x.z = s.z + h.z; x.w = s.w + h.w;
    float sum = x.x + x.y + x.z + x.w;
    float sq  = x.x*x.x + x.y*x.y + x.z*x.z + x.w*x.w;
#pragma unroll
    for (int o = 16; o > 0; o >>= 1) {
        sum += __shfl_xor_sync(0xffffffffu, sum, o);
        sq  += __shfl_xor_sync(0xffffffffu, sq,  o);
    }
    __shared__ float rs[8], rq[8];
    int wid = tid >> 5, lane = tid & 31;
    if (lane == 0) { rs[wid] = sum; rq[wid] = sq; }
    __syncthreads();
    __shared__ float s_mean, s_rstd;
    if (tid == 0) {
        float ts = 0.f, tq = 0.f;
#pragma unroll
        for (int w = 0; w < 8; w++) { ts += rs[w]; tq += rq[w]; }
        float mean = ts / HH;
        float var = tq / HH - mean * mean;
        s_mean = mean;
        s_rstd = rsqrtf(var + 1e-5f);
    }
    __syncthreads();
    float mean = s_mean, rstd = s_rstd;
    int hbase = tid * 4;
    float4 o;
    o.x = (x.x - mean) * rstd * gamma[hbase+0] + beta[hbase+0];
    o.y = (x.y - mean) * rstd * gamma[hbase+1] + beta[hbase+1];
    o.z = (x.z - mean) * rstd * gamma[hbase+2] + beta[hbase+2];
    o.w = (x.w - mean) * rstd * gamma[hbase+3] + beta[hbase+3];
    *(float4*)&out[base] = o;
}

// ---------------------------------------------------------------------------
extern "C" void kernel_launch(void* const* d_in, const int* in_sizes, int n_in,
                              void* d_out, int out_size)
{
    const float* hidden = (const float*)d_in[0];
    const float* Wq = (const float*)d_in[3];
    const float* bq = (const float*)d_in[4];
    const float* W1 = (const float*)d_in[5];
    const float* b1 = (const float*)d_in[6];
    const float* W2 = (const float*)d_in[7];
    const float* b2 = (const float*)d_in[8];
    const float* gamma = (const float*)d_in[9];
    const float* beta  = (const float*)d_in[10];
    float* out = (float*)d_out;

    float *pA = nullptr, *pB = nullptr;
    cudaGetSymbolAddress((void**)&pA, g_stateA);
    cudaGetSymbolAddress((void**)&pB, g_stateB);

    cudaFuncSetAttribute(gemm_tf32_kernel,
                         cudaFuncAttributeMaxDynamicSharedMemorySize, GEMM_SMEM);
    cudaFuncSetAttribute(dots_half_kernel,
                         cudaFuncAttributeMaxDynamicSharedMemorySize, DOTS_SMEM);
    cudaFuncSetAttribute(energy_tiled_kernel,
                         cudaFuncAttributeMaxDynamicSharedMemorySize, ENERGY_SMEM);
    cudaFuncSetAttribute(lapsmooth_kernel,
                         cudaFuncAttributeMaxDynamicSharedMemorySize, LAPS_SMEM);

    gemm_tf32_kernel<<<dim3(HH / TN, (BB * SS) / TM), 256, GEMM_SMEM>>>(hidden, Wq, bq);
    build_tab_kernel<<<(TABD * TABC * 32 + 255) / 256, 256>>>(W1, b1, W2, b2, out);

    // ping-pong: hidden -> A -> B -> A -> B
    const float* srcs[KSTEPS + 1] = { hidden, pA, pB, pA, pB };
    float*       dsts[KSTEPS]     = { pA, pB, pA, pB };

    const int dots_grid = (SS + DT - 1) / DT;       // 86
    const int laps_gx = (SS + LT - 1) / LT;         // 43
    float eta = 0.1f;
    for (int step = 0; step < KSTEPS; step++) {
        dots_half_kernel<<<dim3(dots_grid, BB, 2), 256, DOTS_SMEM>>>(srcs[step]);
        lapsmooth_kernel<<<dim3(laps_gx, HH / LCW, BB), 128, LAPS_SMEM>>>(srcs[step], dsts[step], eta);
        eta *= 0.9f;
    }
    // nsqH/dotsH still hold state_3 values -> mu_3 for energy
    energy_tiled_kernel<<<dim3((SS + EDT - 1) / EDT, BB), 256, ENERGY_SMEM>>>(srcs[KSTEPS], out);
    ln_kernel<<<dim3(SS, BB), 256>>>(srcs[KSTEPS], hidden, gamma, beta, out);
}

// round 13
// speedup vs baseline: 1.3759x; 1.3759x over previous
#include <cuda_runtime.h>
#include <math.h>
#include <stdint.h>

#define BB 4
#define SS 2048
#define HH 1024
#define INNERD 512
#define RAD 8
#define KSTEPS 4
#define LAMv 0.1f
#define MU_MAXV 10.0f

#define BSH (BB*SS*HH)

// mu lookup table: z(dist, cos), pre-softplus.
#define TABD 256
#define TABC 64
#define TAB_HD 0.5f
#define TAB_HC (2.0f / (TABC - 1))

// Scratch (no cudaMalloc allowed). Ping-pong state buffers.
__device__ float g_q[BSH];
__device__ float g_stateA[BSH];
__device__ float g_stateB[BSH];
__device__ float g_nsqH[2 * BB * SS];          // per-column-half partials
__device__ float g_dotsH[2 * BB * RAD * SS];   // per-column-half partials
__device__ float g_mu[BB*RAD*SS];
__device__ float g_ztab[TABD * TABC];

__device__ __forceinline__ float to_tf32(float x) {
    float r;
    asm("cvt.rna.tf32.f32 %0, %1;" : "=f"(r) : "f"(x));
    return r;
}
__device__ __forceinline__ uint32_t tf32_bits(float x) {
    return __float_as_uint(to_tf32(x));
}
__device__ __forceinline__ void cp_async16(uint32_t s, const void* g) {
    asm volatile("cp.async.ca.shared.global [%0], [%1], 16;" :: "r"(s), "l"(g));
}
__device__ __forceinline__ void cp_commit() {
    asm volatile("cp.async.commit_group;");
}
template<int N>
__device__ __forceinline__ void cp_wait() {
    asm volatile("cp.async.wait_group %0;" :: "n"(N));
}

// ---------------------------------------------------------------------------
// GEMM (TF32 mma.sync, cp.async double-buffered): q = hidden @ Wq + bq.
// ---------------------------------------------------------------------------
#define TM 128
#define TN 128
#define TK 32
#define AS_LD (TK + 4)
#define BS_LD (TN + 4)
#define AS_STAGE (TM * AS_LD)
#define BS_STAGE (TK * BS_LD)
#define GEMM_SMEM ((2*AS_STAGE + 2*BS_STAGE) * sizeof(float))

__global__ __launch_bounds__(256) void gemm_tf32_kernel(
    const float* __restrict__ A,
    const float* __restrict__ W,
    const float* __restrict__ bias)
{
    extern __shared__ float sm[];
    float* As = sm;
    float* Bs = sm + 2 * AS_STAGE;
    uint32_t as_u = (uint32_t)__cvta_generic_to_shared(As);
    uint32_t bs_u = (uint32_t)__cvta_generic_to_shared(Bs);

    const int N = HH, K = HH;
    int tid = threadIdx.x;
    int m0 = blockIdx.y * TM;
    int n0 = blockIdx.x * TN;
    int wid = tid >> 5, lane = tid & 31;
    int wm = (wid & 3) * 32;
    int wn = (wid >> 2) * 64;
    int gid = lane >> 2, tig = lane & 3;

    float acc[2][8][4];
#pragma unroll
    for (int mt = 0; mt < 2; mt++)
#pragma unroll
        for (int nt = 0; nt < 8; nt++)
#pragma unroll
            for (int c = 0; c < 4; c++) acc[mt][nt][c] = 0.f;

    int am[4], ak[4], bk[4], bn[4];
#pragma unroll
    for (int r = 0; r < 4; r++) {
        int f = tid + 256 * r;
        am[r] = f >> 3;  ak[r] = (f & 7) * 4;
        bk[r] = f >> 5;  bn[r] = (f & 31) * 4;
    }

#define LOAD_STAGE(s, k0)                                                     \
    {                                                                         \
        _Pragma("unroll")                                                     \
        for (int r = 0; r < 4; r++) {                                         \
            cp_async16(as_u + (((s)*TM + am[r]) * AS_LD + ak[r]) * 4,         \
                       &A[(size_t)(m0 + am[r]) * K + (k0) + ak[r]]);          \
            cp_async16(bs_u + (((s)*TK + bk[r]) * BS_LD + bn[r]) * 4,         \
                       &W[(size_t)((k0) + bk[r]) * N + n0 + bn[r]]);          \
        }                                                                     \
        cp_commit();                                                          \
    }

    LOAD_STAGE(0, 0);

    const int NIT = K / TK;   // 32
    for (int it = 0; it < NIT; it++) {
        if (it + 1 < NIT) {
            LOAD_STAGE((it + 1) & 1, (it + 1) * TK);
            cp_wait<1>();
        } else {
            cp_wait<0>();
        }
        __syncthreads();

        int buf = it & 1;
        const float* Ab = As + buf * AS_STAGE;
        const float* Bb = Bs + buf * BS_STAGE;
#pragma unroll
        for (int ks = 0; ks < 4; ks++) {
            int kb = ks * 8;
            uint32_t af[2][4];
#pragma unroll
            for (int mt = 0; mt < 2; mt++) {
                int rm = wm + mt * 16 + gid;
                af[mt][0] = tf32_bits(Ab[rm * AS_LD + kb + tig]);
                af[mt][1] = tf32_bits(Ab[(rm + 8) * AS_LD + kb + tig]);
                af[mt][2] = tf32_bits(Ab[rm * AS_LD + kb + tig + 4]);
                af[mt][3] = tf32_bits(Ab[(rm + 8) * AS_LD + kb + tig + 4]);
            }
            uint32_t bf[8][2];
#pragma unroll
            for (int nt = 0; nt < 8; nt++) {
                int cn = wn + nt * 8 + gid;
                bf[nt][0] = tf32_bits(Bb[(kb + tig) * BS_LD + cn]);
                bf[nt][1] = tf32_bits(Bb[(kb + tig + 4) * BS_LD + cn]);
            }
#pragma unroll
            for (int mt = 0; mt < 2; mt++)
#pragma unroll
                for (int nt = 0; nt < 8; nt++) {
                    asm volatile(
                        "mma.sync.aligned.m16n8k8.row.col.f32.tf32.tf32.f32 "
                        "{%0,%1,%2,%3}, {%4,%5,%6,%7}, {%8,%9}, {%0,%1,%2,%3};"
                        : "+f"(acc[mt][nt][0]), "+f"(acc[mt][nt][1]),
                          "+f"(acc[mt][nt][2]), "+f"(acc[mt][nt][3])
                        : "r"(af[mt][0]), "r"(af[mt][1]),
                          "r"(af[mt][2]), "r"(af[mt][3]),
                          "r"(bf[nt][0]), "r"(bf[nt][1]));
                }
        }
        __syncthreads();
    }

#pragma unroll
    for (int mt = 0; mt < 2; mt++) {
        int row0 = m0 + wm + mt * 16 + gid;
#pragma unroll
        for (int nt = 0; nt < 8; nt++) {
            int col = n0 + wn + nt * 8 + 2 * tig;
            float bx = bias[col], by = bias[col + 1];
            float2 v0 = make_float2(acc[mt][nt][0] + bx, acc[mt][nt][1] + by);
            float2 v1 = make_float2(acc[mt][nt][2] + bx, acc[mt][nt][3] + by);
            *(float2*)&g_q[(size_t)row0 * N + col] = v0;
            *(float2*)&g_q[(size_t)(row0 + 8) * N + col] = v1;
        }
    }
}

// ---------------------------------------------------------------------------
// Build z-table (runs once). Also zeroes energy slots.
// ---------------------------------------------------------------------------
__global__ __launch_bounds__(256) void build_tab_kernel(
    const float* __restrict__ W1, const float* __restrict__ b1,
    const float* __restrict__ W2, const float* __restrict__ b2,
    float* __restrict__ out)
{
    if (blockIdx.x == 0 && threadIdx.x < BB)
        out[(size_t)BSH + threadIdx.x] = 0.f;

    int w = (blockIdx.x * 256 + threadIdx.x) >> 5;
    int lane = threadIdx.x & 31;
    if (w >= TABD * TABC) return;
    float D = (float)(w / TABC) * TAB_HD;
    float c = -1.f + (float)(w % TABC) * TAB_HC;

    const float IS2 = 0.70710678118654752f;
    float z = 0.f;
#pragma unroll 4
    for (int k = lane; k < INNERD; k += 32) {
        float x = fmaf(D, W1[k], fmaf(c, W1[INNERD + k], b1[k]));
        float g = 0.5f * x * (1.f + erff(x * IS2));
        z = fmaf(g, W2[k], z);
    }
#pragma unroll
    for (int o = 16; o > 0; o >>= 1)
        z += __shfl_xor_sync(0xffffffffu, z, o);
    if (lane == 0) g_ztab[w] = z + b2[0];
}

// ---------------------------------------------------------------------------
// Tiled dots, COLUMN-HALVED: blockIdx.z = half (512 cols). Partial sums into
// g_nsqH / g_dotsH.
// ---------------------------------------------------------------------------
#define DT 24
#define DROWS 32
#define DHALF 512
#define DOTS_SMEM (DROWS * DHALF * sizeof(float))

__global__ __launch_bounds__(256) void dots_half_kernel(const float* __restrict__ src)
{
    extern __shared__ float sh[];  // DROWS * DHALF
    int tid = threadIdx.x;
    int b = blockIdx.y;
    int half = blockIdx.z;
    int i0 = blockIdx.x * DT;
    int cb = half * DHALF;

#pragma unroll
    for (int s = 0; s < (DROWS * DHALF / 4) / 256; s++) {   // 16 iters
        int slot = tid + 256 * s;
        int row = slot >> 7;
        int c4 = slot & 127;
        int i = i0 + row;
        if (i < SS)
            ((float4*)(sh + (size_t)row * DHALF))[c4] =
                ((const float4*)(src + ((size_t)b * SS + i) * HH + cb))[c4];
    }
    __syncthreads();

    int w = tid >> 5, lane = tid & 31;
    size_t hn = (size_t)half * BB * SS;
    size_t hd = (size_t)half * BB * RAD * SS;
#pragma unroll
    for (int nn = 0; nn < 3; nn++) {
        int ln = w * 3 + nn;          // 0..23
        int i = i0 + ln;
        if (i >= SS) continue;
        const float4* arow = (const float4*)(sh + (size_t)ln * DHALF);
        float4 a[4];
#pragma unroll
        for (int r = 0; r < 4; r++) a[r] = arow[lane + 32 * r];

#pragma unroll
        for (int d = 0; d <= RAD; d++) {
            if (d > 0 && i + d >= SS) break;
            float sum = 0.f;
            if (d == 0) {
#pragma unroll
                for (int r = 0; r < 4; r++)
                    sum += a[r].x*a[r].x + a[r].y*a[r].y + a[r].z*a[r].z + a[r].w*a[r].w;
            } else {
                const float4* crow = (const float4*)(sh + (size_t)(ln + d) * DHALF);
#pragma unroll
                for (int r = 0; r < 4; r++) {
                    float4 c = crow[lane + 32 * r];
                    sum += a[r].x*c.x + a[r].y*c.y + a[r].z*c.z + a[r].w*c.w;
                }
            }
#pragma unroll
            for (int o = 16; o > 0; o >>= 1)
                sum += __shfl_xor_sync(0xffffffffu, sum, o);
            if (lane == 0) {
                if (d == 0) g_nsqH[hn + b * SS + i] = sum;
                else g_dotsH[hd + ((size_t)b * RAD + (d - 1)) * SS + i] = sum;
            }
        }
    }
}

// ---------------------------------------------------------------------------
// mu via table lookup (sums the two column-half partials).
// ---------------------------------------------------------------------------
__global__ __launch_bounds__(256) void mu_lookup_kernel()
{
    int e = blockIdx.x * 256 + threadIdx.x;   // < BB*RAD*SS
    int b = e >> 14;
    int r = e & 16383;
    int d = (r >> 11) + 1;
    int i = r & 2047;
    size_t slot = ((size_t)b * RAD + (d - 1)) * SS + i;
    if (i + d >= SS) { g_mu[slot] = 0.f; return; }

    float nsqi = g_nsqH[b * SS + i] + g_nsqH[(size_t)BB * SS + b * SS + i];
    float nsqj = g_nsqH[b * SS + i + d] + g_nsqH[(size_t)BB * SS + b * SS + i + d];
    float dot  = g_dotsH[slot] + g_dotsH[(size_t)BB * RAD * SS + slot];
    float dist = sqrtf(fmaxf(nsqi + nsqj - 2.f * dot, 0.f));
    float ni = fmaxf(sqrtf(nsqi), 1e-6f);
    float nj = fmaxf(sqrtf(nsqj), 1e-6f);
    float cosv = dot / (ni * nj);

    float Df = dist * (1.f / TAB_HD);
    int di = (int)Df;
    di = min(max(di, 0), TABD - 2);
    float fd = fminf(fmaxf(Df - (float)di, 0.f), 1.f);

    float Cf = (cosv + 1.f) * (1.f / TAB_HC);
    int cj = (int)Cf;
    cj = min(max(cj, 0), TABC - 2);
    float fc = fminf(fmaxf(Cf - (float)cj, 0.f), 1.f);

    const float* t0 = &g_ztab[di * TABC + cj];
    float z00 = t0[0],        z01 = t0[1];
    float z10 = t0[TABC],     z11 = t0[TABC + 1];
    float zl = z00 + fc * (z01 - z00);
    float zh = z10 + fc * (z11 - z10);
    float z  = zl + fd * (zh - zl);

    float sp = fmaxf(z, 0.f) + log1pf(expf(-fabsf(z)));
    g_mu[slot] = fminf(sp + 1e-5f, MU_MAXV);
}

// ---------------------------------------------------------------------------
// Fused deg+lap+update+smooth, REGISTER-STREAMING: no state smem tile.
// Each thread owns 2 columns; 17-row state window in a register ring.
// Block = 256 threads (512 cols); grid (SS/LT, HH/512, BB) = 1024 blocks.
// ---------------------------------------------------------------------------
#define LT 16
#define LTROWS (LT + 2)      // 18 tmp rows
#define LSROWS (LT + 18)     // 34 isq window rows [i0-9, i0+25)

__global__ __launch_bounds__(256, 3) void lapsmooth_kernel(
    const float* __restrict__ src, float* __restrict__ dst, float eta)
{
    __shared__ float cof[LTROWS * 16];
    __shared__ float csm[LTROWS];
    __shared__ float isqs[LSROWS];

    int tid = threadIdx.x;
    int b = blockIdx.z;
    int i0 = blockIdx.x * LT;
    int cb = blockIdx.y * 512;
    int col = cb + tid * 2;

    // fused deg: isq for nodes [i0-9, i0+25)
    if (tid < LSROWS) {
        int n = i0 - 9 + tid;
        float isq = 0.f;
        if (n >= 0 && n < SS) {
            float deg = 0.f;
#pragma unroll
            for (int d = 1; d <= RAD; d++) {
                if (n + d < SS) deg += g_mu[((size_t)b * RAD + (d - 1)) * SS + n];
                if (n >= d)     deg += g_mu[((size_t)b * RAD + (d - 1)) * SS + n - d];
            }
            isq = rsqrtf(fmaxf(deg, 1e-6f));
        }
        isqs[tid] = isq;
    }
    __syncthreads();

    // coefficients for 18 tmp rows (clamped je)
    for (int idx = tid; idx < LTROWS * 16; idx += 256) {
        int jl = idx >> 4;
        int k = idx & 15;
        int j = i0 - 1 + jl;
        int je = min(max(j, 0), SS - 1);
        int d = (k >> 1) + 1;
        float c = 0.f;
        if (!(k & 1)) {
            int jn = je + d;
            if (jn < SS)
                c = g_mu[((size_t)b * RAD + (d - 1)) * SS + je] *
                    isqs[je - (i0 - 9)] * isqs[min(jn - (i0 - 9), LSROWS - 1)];
        } else {
            int jn = je - d;
            if (jn >= 0)
                c = g_mu[((size_t)b * RAD + (d - 1)) * SS + jn] *
                    isqs[je - (i0 - 9)] * isqs[max(jn - (i0 - 9), 0)];
        }
        cof[idx] = c;
    }
    __syncthreads();
    if (tid < LTROWS) {
        float s = 0.f;
#pragma unroll
        for (int k = 0; k < 16; k++) s += cof[tid * 16 + k];
        csm[tid] = s;
    }
    __syncthreads();

    const float* sb = src + (size_t)b * SS * HH + col;
    const float* qb = g_q + (size_t)b * SS * HH + col;
    float*       db = dst + (size_t)b * SS * HH + col;

    // register ring: slot of logical row r is (r - (i0-9)) % 17
    float2 ring[17];
#pragma unroll
    for (int c = 0; c < 17; c++) {
        int j = min(max(i0 - 9 + c, 0), SS - 1);
        ring[c] = *(const float2*)&sb[(size_t)j * HH];
    }

    float2 t0, t1, t2;
#pragma unroll
    for (int jl = 0; jl < LTROWS; jl++) {
        float2 si = ring[(jl + 8) % 17];      // logical row i0-1+jl (clamped load)
        float cs = csm[jl];
        float2 acc;
        acc.x = cs * si.x; acc.y = cs * si.y;
#pragma unroll
        for (int k = 0; k < 16; k++) {
            float c = cof[jl * 16 + k];
            if (c != 0.f) {
                int d = (k >> 1) + 1;
                int off = (k & 1) ? -d : d;
                float2 sj = ring[(jl + 8 + off + 17) % 17];
                acc.x = fmaf(-c, sj.x, acc.x);
                acc.y = fmaf(-c, sj.y, acc.y);
            }
        }
        int je = min(max(i0 - 1 + jl, 0), SS - 1);
        float2 qv = *(const float2*)&qb[(size_t)je * HH];
        float2 tv;
        tv.x = si.x - eta * (acc.x - qv.x);
        tv.y = si.y - eta * (acc.y - qv.y);
        t0 = t1; t1 = t2; t2 = tv;
        if (jl >= 2) {
            int i = i0 + jl - 2;
            float2 o;
            o.x = t1.x - LAMv * (2.f * t1.x - t0.x - t2.x);
            o.y = t1.y - LAMv * (2.f * t1.y - t0.y - t2.y);
            *(float2*)&db[(size_t)i * HH] = o;
        }
        // slide window: bring in logical row i0+8+jl at slot jl%17
        if (jl + 1 < LTROWS) {
            int jn = min(i0 + 8 + jl, SS - 1);
            ring[jl % 17] = *(const float2*)&sb[(size_t)jn * HH];
        }
    }
}

// ---------------------------------------------------------------------------
// Fused final energy: per tile, energy += 0.5 * sum mu_e * ||s_i - s_j||^2.
// ---------------------------------------------------------------------------
#define EROWS 32
#define EDT 24
#define ENERGY_SMEM (EROWS * HH * sizeof(float))

__global__ __launch_bounds__(256) void energy_tiled_kernel(
    const float* __restrict__ src, float* __restrict__ out)
{
    extern __shared__ float sh[];  // EROWS * HH
    int tid = threadIdx.x;
    int b = blockIdx.y;
    int i0 = blockIdx.x * EDT;

#pragma unroll
    for (int r = 0; r < EROWS; r++) {
        int i = i0 + r;
        if (i < SS)
            ((float4*)(sh + (size_t)r * HH))[tid] =
                ((const float4*)(src + ((size_t)b * SS + i) * HH))[tid];
    }
    __syncthreads();

    int w = tid >> 5, lane = tid & 31;
    float wpart = 0.f;
#pragma unroll
    for (int nn = 0; nn < 3; nn++) {
        int ln = w * 3 + nn;
        int i = i0 + ln;
        if (i >= SS) continue;
        const float4* arow = (const float4*)(sh + (size_t)ln * HH);
        float4 a[8];
#pragma unroll
        for (int r = 0; r < 8; r++) a[r] = arow[lane + 32 * r];
#pragma unroll
        for (int d = 1; d <= RAD; d++) {
            if (i + d >= SS) break;
            const float4* crow = (const float4*)(sh + (size_t)(ln + d) * HH);
            float sum = 0.f;
#pragma unroll
            for (int r = 0; r < 8; r++) {
                float4 c = crow[lane + 32 * r];
                float dx = a[r].x - c.x, dy = a[r].y - c.y;
                float dz = a[r].z - c.z, dw = a[r].w - c.w;
                sum += dx*dx + dy*dy + dz*dz + dw*dw;
            }
#pragma unroll
            for (int o = 16; o > 0; o >>= 1)
                sum += __shfl_xor_sync(0xffffffffu, sum, o);
            if (lane == 0)
                wpart += g_mu[((size_t)b * RAD + (d - 1)) * SS + i] * sum;
        }
    }
    __shared__ float red[8];
    if (lane == 0) red[w] = wpart;
    __syncthreads();
    if (tid == 0) {
        float s = 0.f;
#pragma unroll
        for (int ww = 0; ww < 8; ww++) s += red[ww];
        atomicAdd(&out[(size_t)BSH + b], 0.5f * s);
    }
}

// ---------------------------------------------------------------------------
// out = layernorm(final + hidden) * gamma + beta
// ---------------------------------------------------------------------------
__global__ __launch_bounds__(256) void ln_kernel(
    const float* __restrict__ fin,
    const float* __restrict__ hidden,
    const float* __restrict__ gamma, const float* __restrict__ beta,
    float* __restrict__ out)
{
    int i = blockIdx.x, b = blockIdx.y;
    int tid = threadIdx.x;
    size_t base = ((size_t)b * SS + i) * HH + tid * 4;
    float4 s = *(const float4*)&fin[base];
    float4 h = *(const float4*)&hidden[base];
    float4 x;
    x.x = s.x + h.x; x.y = s.y + h.y; x.z = s.z + h.z; x.w = s.w + h.w;
    float sum = x.x + x.y + x.z + x.w;
    float sq  = x.x*x.x + x.y*x.y + x.z*x.z + x.w*x.w;
#pragma unroll
    for (int o = 16; o > 0; o >>= 1) {
        sum += __shfl_xor_sync(0xffffffffu, sum, o);
        sq  += __shfl_xor_sync(0xffffffffu, sq,  o);
    }
    __shared__ float rs[8], rq[8];
    int wid = tid >> 5, lane = tid & 31;
    if (lane == 0) { rs[wid] = sum; rq[wid] = sq; }
    __syncthreads();
    __shared__ float s_mean, s_rstd;
    if (tid == 0) {
        float ts = 0.f, tq = 0.f;
#pragma unroll
        for (int w = 0; w < 8; w++) { ts += rs[w]; tq += rq[w]; }
        float mean = ts / HH;
        float var = tq / HH - mean * mean;
        s_mean = mean;
        s_rstd = rsqrtf(var + 1e-5f);
    }
    __syncthreads();
    float mean = s_mean, rstd = s_rstd;
    int hbase = tid * 4;
    float4 o;
    o.x = (x.x - mean) * rstd * gamma[hbase+0] + beta[hbase+0];
    o.y = (x.y - mean) * rstd * gamma[hbase+1] + beta[hbase+1];
    o.z = (x.z - mean) * rstd * gamma[hbase+2] + beta[hbase+2];
    o.w = (x.w - mean) * rstd * gamma[hbase+3] + beta[hbase+3];
    *(float4*)&out[base] = o;
}

// ---------------------------------------------------------------------------
extern "C" void kernel_launch(void* const* d_in, const int* in_sizes, int n_in,
                              void* d_out, int out_size)
{
    const float* hidden = (const float*)d_in[0];
    const float* Wq = (const float*)d_in[3];
    const float* bq = (const float*)d_in[4];
    const float* W1 = (const float*)d_in[5];
    const float* b1 = (const float*)d_in[6];
    const float* W2 = (const float*)d_in[7];
    const float* b2 = (const float*)d_in[8];
    const float* gamma = (const float*)d_in[9];
    const float* beta  = (const float*)d_in[10];
    float* out = (float*)d_out;

    float *pA = nullptr, *pB = nullptr;
    cudaGetSymbolAddress((void**)&pA, g_stateA);
    cudaGetSymbolAddress((void**)&pB, g_stateB);

    cudaFuncSetAttribute(gemm_tf32_kernel,
                         cudaFuncAttributeMaxDynamicSharedMemorySize, GEMM_SMEM);
    cudaFuncSetAttribute(dots_half_kernel,
                         cudaFuncAttributeMaxDynamicSharedMemorySize, DOTS_SMEM);
    cudaFuncSetAttribute(energy_tiled_kernel,
                         cudaFuncAttributeMaxDynamicSharedMemorySize, ENERGY_SMEM);

    gemm_tf32_kernel<<<dim3(HH / TN, (BB * SS) / TM), 256, GEMM_SMEM>>>(hidden, Wq, bq);
    build_tab_kernel<<<(TABD * TABC * 32 + 255) / 256, 256>>>(W1, b1, W2, b2, out);

    // ping-pong: hidden -> A -> B -> A -> B
    const float* srcs[KSTEPS + 1] = { hidden, pA, pB, pA, pB };
    float*       dsts[KSTEPS]     = { pA, pB, pA, pB };

    const int dots_grid = (SS + DT - 1) / DT;   // 86
    float eta = 0.1f;
    for (int step = 0; step < KSTEPS; step++) {
        dots_half_kernel<<<dim3(dots_grid, BB, 2), 256, DOTS_SMEM>>>(srcs[step]);
        mu_lookup_kernel<<<(BB * RAD * SS) / 256, 256>>>();
        lapsmooth_kernel<<<dim3(SS / LT, HH / 512, BB), 256>>>(srcs[step], dsts[step], eta);
        eta *= 0.9f;
    }
    energy_tiled_kernel<<<dim3((SS + EDT - 1) / EDT, BB), 256, ENERGY_SMEM>>>(srcs[KSTEPS], out);
    ln_kernel<<<dim3(SS, BB), 256>>>(srcs[KSTEPS], hidden, gamma, beta, out);
}